// round 1
// baseline (speedup 1.0000x reference)
#include <cuda_runtime.h>
#include <cuda_bf16.h>

// SABR implied vol with BETA=1, R=Q=0 degeneracies:
//   out[e][t][j] = v * B_t(v) * G_j(v)
//   B_t = 1 + t*(c1*v + c2),  c1 = RHO*VOLVOL/4 = -0.0525, c2 = VOLVOL^2*(2-3RHO^2)/24
//   G_j = Phi_j / (Chi_j + 1e-8), Phi_j = 0.3 * L_j / v,  L_j = -ln(m_j)
//   Chi_j = ln( (sqrt(1 + 1.4*Phi + Phi^2) + Phi + 0.7) / 1.7 )
//   j == 2 (m = 1.0): F == K branch -> v * B_t  (G = 1)
// price input is mathematically unused.

#define BLK 256

__global__ __launch_bounds__(BLK)
void sabr_kernel(const float* __restrict__ vol, float* __restrict__ out, int n)
{
    __shared__ float sm[BLK * 25];

    const int tid = threadIdx.x;
    const long long base = (long long)blockIdx.x * BLK;
    const int e = (int)base + tid;

    float* row = sm + tid * 25;   // stride 25 (odd) -> bank-conflict-free

    if (e < n) {
        const float v = vol[e];

        // B_t = 1 + t*slope
        const float slope = fmaf(-0.0525f, v, 0.0019875f);
        float b[5];
        #pragma unroll
        for (int t = 0; t < 5; ++t) b[t] = fmaf((float)t, slope, 1.0f);

        // G_j for the four m != 1 columns
        const float u = __fdividef(0.3f, v);       // VOLVOL / v
        const float L[4] = { 0.35667494f,   // -ln(0.70)
                             0.16251893f,   // -ln(0.85)
                            -0.13976194f,   // -ln(1.15)
                            -0.26236426f }; // -ln(1.30)
        float g[5];
        g[2] = 1.0f;
        #pragma unroll
        for (int jj = 0; jj < 4; ++jj) {
            const float Phi = u * L[jj];
            // 1 - 2*rho*Phi + Phi^2 = 1 + 1.4*Phi + Phi^2  (always > 0)
            const float h   = fmaf(Phi, Phi, fmaf(1.4f, Phi, 1.0f));
            const float q   = sqrtf(h) + Phi + 0.7f;          // + (Phi - rho)
            const float Chi = __logf(q * 0.5882353f);          // ln(q / 1.7)
            const int j = (jj < 2) ? jj : jj + 1;
            g[j] = __fdividef(Phi, Chi + 1e-8f);
        }

        #pragma unroll
        for (int t = 0; t < 5; ++t) {
            const float vb = v * b[t];
            #pragma unroll
            for (int j = 0; j < 5; ++j)
                row[t * 5 + j] = vb * g[j];
        }
    } else {
        #pragma unroll
        for (int k = 0; k < 25; ++k) row[k] = 0.0f;
    }

    __syncthreads();

    // Coalesced flush: linear layout [e][k] == linear index k'*BLK + tid
    float* __restrict__ gout = out + base * 25;
    const long long lim = (long long)n * 25 - base * 25;
    #pragma unroll
    for (int k = 0; k < 25; ++k) {
        const int idx = k * BLK + tid;
        if (idx < lim) gout[idx] = sm[idx];
    }
}

extern "C" void kernel_launch(void* const* d_in, const int* in_sizes, int n_in,
                              void* d_out, int out_size)
{
    const float* vol = (const float*)d_in[0];   // metadata order: vol, price
    float* out = (float*)d_out;
    const int n = in_sizes[0];                  // 4096*512 = 2,097,152
    const int blocks = (n + BLK - 1) / BLK;
    sabr_kernel<<<blocks, BLK>>>(vol, out, n);
}

// round 2
// speedup vs baseline: 1.1185x; 1.1185x over previous
#include <cuda_runtime.h>
#include <cuda_bf16.h>

// SABR implied vol with BETA=1, R=Q=0 degeneracies:
//   out[e][t][j] = v * B_t(v) * G_j(v)
//   B_t = 1 + t*(c1*v + c2),  c1 = RHO*VOLVOL/4 = -0.0525, c2 = VOLVOL^2*(2-3RHO^2)/24
//   G_j = Phi_j / (Chi_j + 1e-8), Phi_j = 0.3 * L_j / v,  L_j = -ln(m_j)
//   Chi_j = ln( (sqrt(1 + 1.4*Phi + Phi^2) + Phi + 0.7) / 1.7 )
//   j == 2 (m = 1.0): F == K -> G = 1.  price input mathematically unused.
//
// R2: float4 shared->global flush (25 scalar STG -> 7 STG.128) + __stcs
// streaming stores. Attacks L1/issue contention (59.6%/57.7%) that was
// capping DRAM at 56.8%.

#define BLK 256

__global__ __launch_bounds__(BLK)
void sabr_kernel(const float* __restrict__ vol, float* __restrict__ out, int n)
{
    __shared__ __align__(16) float sm[BLK * 25];

    const int tid = threadIdx.x;
    const long long base = (long long)blockIdx.x * BLK;
    const int e = (int)base + tid;

    float* row = sm + tid * 25;   // stride 25 (odd) -> bank-conflict-free STS

    if (e < n) {
        const float v = vol[e];

        // B_t = 1 + t*slope
        const float slope = fmaf(-0.0525f, v, 0.0019875f);
        float b[5];
        #pragma unroll
        for (int t = 0; t < 5; ++t) b[t] = fmaf((float)t, slope, 1.0f);

        // G_j for the four m != 1 columns
        const float u = __fdividef(0.3f, v);       // VOLVOL / v
        const float L[4] = { 0.35667494f,   // -ln(0.70)
                             0.16251893f,   // -ln(0.85)
                            -0.13976194f,   // -ln(1.15)
                            -0.26236426f }; // -ln(1.30)
        float g[5];
        g[2] = 1.0f;
        #pragma unroll
        for (int jj = 0; jj < 4; ++jj) {
            const float Phi = u * L[jj];
            // 1 - 2*rho*Phi + Phi^2 = 1 + 1.4*Phi + Phi^2  (always > 0)
            const float h   = fmaf(Phi, Phi, fmaf(1.4f, Phi, 1.0f));
            const float q   = sqrtf(h) + Phi + 0.7f;          // + (Phi - rho)
            const float Chi = __logf(q * 0.5882353f);          // ln(q / 1.7)
            const int j = (jj < 2) ? jj : jj + 1;
            g[j] = __fdividef(Phi, Chi + 1e-8f);
        }

        #pragma unroll
        for (int t = 0; t < 5; ++t) {
            const float vb = v * b[t];
            #pragma unroll
            for (int j = 0; j < 5; ++j)
                row[t * 5 + j] = vb * g[j];
        }
    } else {
        #pragma unroll
        for (int k = 0; k < 25; ++k) row[k] = 0.0f;
    }

    __syncthreads();

    // Flush: linear layout [e][k] in shared == linear output index.
    if (base + BLK <= (long long)n) {
        // Full block: vectorized float4 flush. 6400 floats = 1600 float4:
        // 6 full rounds of 256 + 64 extra.
        const float4* __restrict__ s4 = (const float4*)sm;
        float4* __restrict__ g4 = (float4*)(out + base * 25);
        #pragma unroll
        for (int k = 0; k < 6; ++k)
            __stcs(&g4[k * BLK + tid], s4[k * BLK + tid]);
        if (tid < 64)
            __stcs(&g4[6 * BLK + tid], s4[6 * BLK + tid]);
    } else {
        // Tail block: scalar flush with bounds check.
        float* __restrict__ gout = out + base * 25;
        const long long lim = (long long)n * 25 - base * 25;
        #pragma unroll
        for (int k = 0; k < 25; ++k) {
            const int idx = k * BLK + tid;
            if (idx < lim) gout[idx] = sm[idx];
        }
    }
}

extern "C" void kernel_launch(void* const* d_in, const int* in_sizes, int n_in,
                              void* d_out, int out_size)
{
    const float* vol = (const float*)d_in[0];   // metadata order: vol, price
    float* out = (float*)d_out;
    const int n = in_sizes[0];                  // 4096*512 = 2,097,152
    const int blocks = (n + BLK - 1) / BLK;
    sabr_kernel<<<blocks, BLK>>>(vol, out, n);
}